// round 15
// baseline (speedup 1.0000x reference)
#include <cuda_runtime.h>
#include <cuda_fp16.h>
#include <stdint.h>

#define B_ 4096
#define I_ 256
#define H_ 1024
#define N4H 4096
#define M_ 4
#define EPSM 1e-2f
#define CAPF (1<<20)
#define BN_SZ ((size_t)B_*N4H)

// ---------------- device scratch ----------------
__device__ float    g_wf32_ih[M_*N4H*I_];
__device__ float    g_wf32_hh[M_*N4H*H_];
__device__ uint32_t g_w16_ih[M_*N4H*I_];
__device__ uint32_t g_w16_hh[M_*N4H*H_];
__device__ uint32_t g_aex_ih[(size_t)M_*B_*I_];   // pre-expanded A planes
__device__ uint32_t g_aex_hh[(size_t)M_*B_*H_];
__device__ float g_bq_ih[M_*N4H], g_bn_ih[M_*N4H], g_bq_hh[M_*N4H], g_bn_hh[M_*N4H];
__device__ unsigned char g_code_in[B_*I_], g_code_hx[B_*H_];
__device__ unsigned char g_pb_ih[4*BN_SZ];
__device__ unsigned char g_pb_hh[4*BN_SZ];
__device__ float g_max[4];
__device__ int g_cnt[2];
__device__ int g_dnb[8][32];
__device__ int g_mdone[2];
__device__ int g_fdone[2];
__device__ int g_edone[2];
__device__ int g_pdone, g_cdone, g_bdone;
__device__ uint32_t g_list0[CAPF], g_list1[CAPF];

// ---------------- threefry2x32 (JAX exact) ----------------
__host__ __device__ __forceinline__ uint32_t rotl32(uint32_t x, int r) {
    return (x << r) | (x >> (32 - r));
}
__host__ __device__ __forceinline__ void tf2x32(uint32_t k0, uint32_t k1,
                                                uint32_t x0, uint32_t x1,
                                                uint32_t* o0, uint32_t* o1) {
    uint32_t ks0 = k0, ks1 = k1, ks2 = k0 ^ k1 ^ 0x1BD11BDAu;
    x0 += ks0; x1 += ks1;
#define TF_RND(r) { x0 += x1; x1 = rotl32(x1, r); x1 ^= x0; }
    TF_RND(13) TF_RND(15) TF_RND(26) TF_RND(6)
    x0 += ks1; x1 += ks2 + 1u;
    TF_RND(17) TF_RND(29) TF_RND(16) TF_RND(24)
    x0 += ks2; x1 += ks0 + 2u;
    TF_RND(13) TF_RND(15) TF_RND(26) TF_RND(6)
    x0 += ks0; x1 += ks1 + 3u;
    TF_RND(17) TF_RND(29) TF_RND(16) TF_RND(24)
    x0 += ks1; x1 += ks2 + 4u;
    TF_RND(13) TF_RND(15) TF_RND(26) TF_RND(6)
    x0 += ks2; x1 += ks0 + 5u;
#undef TF_RND
    *o0 = x0; *o1 = x1;
}
__device__ __forceinline__ uint32_t rotl_mul(uint32_t x, int r) {
    uint64_t p = (uint64_t)x * (uint64_t)(1u << r);
    return (uint32_t)p | (uint32_t)(p >> 32);
}
__device__ __forceinline__ void tf2x32_bal(uint32_t k0, uint32_t k1,
                                           uint32_t x0, uint32_t x1,
                                           uint32_t* o0, uint32_t* o1) {
    uint32_t ks0 = k0, ks1 = k1, ks2 = k0 ^ k1 ^ 0x1BD11BDAu;
    x0 += ks0; x1 += ks1;
#define RA(r) { x0 += x1; x1 = rotl_mul(x1, r) ^ x0; }
#define RB(r) { x0 += x1; x1 = rotl32(x1, r) ^ x0; }
    RA(13) RB(15) RA(26) RB(6)
    x0 += ks1; x1 += ks2 + 1u;
    RA(17) RB(29) RA(16) RB(24)
    x0 += ks2; x1 += ks0 + 2u;
    RA(13) RB(15) RA(26) RB(6)
    x0 += ks0; x1 += ks1 + 3u;
    RA(17) RB(29) RA(16) RB(24)
    x0 += ks1; x1 += ks2 + 4u;
    RA(13) RB(15) RA(26) RB(6)
    x0 += ks2; x1 += ks0 + 5u;
#undef RA
#undef RB
    *o0 = x0; *o1 = x1;
}

__device__ __forceinline__ float erfinv_xla(float x) {
    float w = -log1pf(-__fmul_rn(x, x));
    float p;
    if (w < 5.0f) {
        w = w - 2.5f;
        p = 2.81022636e-08f;
        p = fmaf(p, w, 3.43273939e-07f);
        p = fmaf(p, w, -3.5233877e-06f);
        p = fmaf(p, w, -4.39150654e-06f);
        p = fmaf(p, w, 0.00021858087f);
        p = fmaf(p, w, -0.00125372503f);
        p = fmaf(p, w, -0.00417768164f);
        p = fmaf(p, w, 0.246640727f);
        p = fmaf(p, w, 1.50140941f);
    } else {
        w = sqrtf(w) - 3.0f;
        p = -0.000200214257f;
        p = fmaf(p, w, 0.000100950558f);
        p = fmaf(p, w, 0.00134934322f);
        p = fmaf(p, w, -0.00367342844f);
        p = fmaf(p, w, 0.00573950773f);
        p = fmaf(p, w, -0.0076224613f);
        p = fmaf(p, w, 0.00943887047f);
        p = fmaf(p, w, 1.00167406f);
        p = fmaf(p, w, 2.83297682f);
    }
    return __fmul_rn(p, x);
}
__device__ __forceinline__ float normal_from_bits(uint32_t bits) {
    float f = __uint_as_float((bits >> 9) | 0x3f800000u) - 1.0f;
    const float lo = -0.99999994f;
    float u = fmaxf(lo, __fadd_rn(__fmul_rn(f, 2.0f), lo));
    return __fmul_rn(1.41421356f, erfinv_xla(u));
}
__device__ __forceinline__ float quant8(float x) {
    float xs = fminf(fmaxf(x, -0.9921875f), 0.9921875f);
    return __fmul_rn(rintf(__fmul_rn(xs, 128.0f)), 0.0078125f);
}
__device__ __forceinline__ float weff_val(const float* W, int j, uint32_t k0,
                                          uint32_t k1, float wmax) {
    uint32_t o0, o1;
    tf2x32_bal(k0, k1, 0u, (uint32_t)j, &o0, &o1);
    float nrm = normal_from_bits(o0 ^ o1);
    return __fadd_rn(quant8(W[j]), __fmul_rn(__fmul_rn(nrm, wmax), 0.1f));
}

// ---------------- PTX helpers ----------------
__device__ __forceinline__ uint32_t smem_u32(const void* p) {
    uint32_t a;
    asm("{ .reg .u64 t; cvta.to.shared.u64 t, %1; cvt.u32.u64 %0, t; }" : "=r"(a) : "l"(p));
    return a;
}
__device__ __forceinline__ void cpa16(uint32_t dst, const void* src) {
    asm volatile("cp.async.cg.shared.global [%0], [%1], 16;" :: "r"(dst), "l"(src));
}
#define CPA_COMMIT() asm volatile("cp.async.commit_group;" ::: "memory")
#define LDMX4(r, a) asm volatile( \
    "ldmatrix.sync.aligned.m8n8.x4.shared.b16 {%0,%1,%2,%3}, [%4];" \
    : "=r"((r)[0]), "=r"((r)[1]), "=r"((r)[2]), "=r"((r)[3]) : "r"(a))
#define HMMA(c, a, bb0, bb1) asm volatile( \
    "mma.sync.aligned.m16n8k16.row.col.f32.f16.f16.f32 " \
    "{%0,%1,%2,%3},{%4,%5,%6,%7},{%8,%9},{%0,%1,%2,%3};" \
    : "+f"((c)[0]), "+f"((c)[1]), "+f"((c)[2]), "+f"((c)[3]) \
    : "r"((a)[0]), "r"((a)[1]), "r"((a)[2]), "r"((a)[3]), "r"(bb0), "r"(bb1))

__device__ __forceinline__ void spinv(volatile int* p, int target) {
    if (threadIdx.x == 0) {
        while (*p < target) __nanosleep(100);
        __threadfence();
    }
    __syncthreads();
}

// ---------------- init ----------------
__global__ void k_init() {
    int t = threadIdx.x;
    if (t < 4) g_max[t] = 0.0f;
    if (t < 2) { g_cnt[t] = 0; g_mdone[t] = 0; g_fdone[t] = 0; g_edone[t] = 0; }
    if (t == 0) { g_pdone = 0; g_cdone = 0; g_bdone = 0; }
    ((int*)g_dnb)[t] = 0;
}

// ---------------- role: max reductions ----------------
__device__ void do_maxred(int lb, int nct, const float* __restrict__ x, int n,
                          int slot) {
    float mm = 0.0f;
    for (int i = lb * 256 + threadIdx.x; i < n; i += nct * 256)
        mm = fmaxf(mm, x[i]);
    for (int o = 16; o; o >>= 1)
        mm = fmaxf(mm, __shfl_xor_sync(0xffffffffu, mm, o));
    if ((threadIdx.x & 31) == 0)
        atomicMax((int*)&g_max[slot], __float_as_int(mm));
    __threadfence();
    __syncthreads();
    if (threadIdx.x == 0) atomicAdd(&g_pdone, 1);
}

// ---------------- role: activation codes ----------------
__device__ void do_code(int lb, const float* __restrict__ x,
                        unsigned char* __restrict__ code,
                        const float* aclip, const float* aoff) {
    float ac = aclip[0], off = aoff[0];
    float den = __fmul_rn(ac, 2.0f);
    for (int i = threadIdx.x; i < 4096; i += 256) {
        int idx = lb * 4096 + i;
        float xc = fminf(fmaxf(x[idx], -ac), ac);
        float v01 = __fdiv_rn(__fadd_rn(xc, off), den);
        int v = (int)rintf(__fmul_rn(15.0f, v01));
        code[idx] = (unsigned char)(v & 15);
    }
    __threadfence();
    __syncthreads();
    if (threadIdx.x == 0) atomicAdd(&g_cdone, 1);
}

// ---------------- role: bias gen ----------------
__device__ void do_genb(int lb, const float* __restrict__ bsrc,
                        float* __restrict__ bq, float* __restrict__ bn,
                        uint32_t k0, uint32_t k1, int maxslot) {
    spinv(&g_pdone, 264);
    int j = lb * 256 + threadIdx.x;
    uint32_t o0, o1;
    tf2x32_bal(k0, k1, 0u, (uint32_t)j, &o0, &o1);
    float nrm = normal_from_bits(o0 ^ o1);
    float wmax = *((volatile float*)&g_max[maxslot]);
    bq[j] = quant8(bsrc[j]);
    bn[j] = __fmul_rn(__fmul_rn(nrm, wmax), 0.1f);
    __threadfence();
    __syncthreads();
    if (threadIdx.x == 0) atomicAdd(&g_bdone, 1);
}

// ---------------- role: A-plane expansion (code byte -> fp16-pair word) ------
__device__ void do_expand(int lb, const unsigned char* __restrict__ codes,
                          uint32_t* __restrict__ aex, size_t total, int eslot) {
    spinv(&g_cdone, 1280);
    size_t base = (size_t)lb * 8192 + (size_t)threadIdx.x * 32;
    uint4 c0 = *(const uint4*)(codes + base);
    uint4 c1 = *(const uint4*)(codes + base + 16);
    uint32_t w[8] = {c0.x, c0.y, c0.z, c0.w, c1.x, c1.y, c1.z, c1.w};
#pragma unroll
    for (int m = 0; m < 4; m++) {
        int shift = 3 - m;
        uint32_t out[32];
#pragma unroll
        for (int i = 0; i < 32; i++)
            out[i] = ((w[i >> 2] >> ((i & 3) * 8 + shift)) & 1u) ? 0x3C003C00u : 0u;
        uint4* dst = (uint4*)(aex + (size_t)m * total + base);
#pragma unroll
        for (int q = 0; q < 8; q++)
            dst[q] = *(uint4*)&out[q * 4];
    }
    __threadfence();
    __syncthreads();
    if (threadIdx.x == 0) atomicAdd(&g_edone[eslot], 1);
}

// ---------------- role: weight gen (smem transpose, coalesced stores) --------
__device__ void do_gen(char* dsm, const float* __restrict__ W,
                       float* __restrict__ wf32, uint32_t* __restrict__ w16, int K,
                       uint32_t key0, uint32_t key1, int maxslot,
                       int m, int kt, int nt, int dnbrow) {
    spinv(&g_pdone, 264);
    float (*tf)[33] = (float(*)[33])dsm;
    uint32_t (*th)[33] = (uint32_t(*)[33])(dsm + 4224);
    const int tid = threadIdx.x;
    const int kk0 = kt * 32, nn0 = nt * 32;
    const int tx = tid & 31, ty = tid >> 5;
    const float wmax = *((volatile float*)&g_max[maxslot]);
#pragma unroll
    for (int r = ty; r < 32; r += 8) {
        int j = (m * K + kk0 + r) * N4H + nn0 + tx;
        float w = weff_val(W, j, key0, key1, wmax);
        __half hi = __float2half_rn(w);
        float r1 = __fsub_rn(w, __half2float(hi));
        __half lo = __float2half_rn(r1);
        tf[r][tx] = w;
        th[r][tx] = (uint32_t)__half_as_ushort(hi) |
                    ((uint32_t)__half_as_ushort(lo) << 16);
    }
    __syncthreads();
#pragma unroll
    for (int r = ty; r < 32; r += 8) {
        size_t base = ((size_t)m * N4H + nn0 + r) * K + kk0 + tx;
        wf32[base] = tf[tx][r];
        w16[base] = th[tx][r];
    }
    __threadfence();
    __syncthreads();
    if (tid == 0) atomicAdd(&g_dnb[dnbrow][nt >> 2], 1);
}

// ---------------- role: HMMA 128x128 tile (A from pre-expanded planes) -------
__device__ void do_mma(char* sm, const uint32_t* __restrict__ aexbase, int K,
                       const uint32_t* __restrict__ w16,
                       const float* __restrict__ bq, const float* __restrict__ bn,
                       unsigned char* __restrict__ pb,
                       uint32_t* __restrict__ list, int* __restrict__ cnt,
                       int mstart, int mend, int dnbrow0, int nbtarget,
                       int n0, int b0, int mdslot, int eslot, int etarget) {
    spinv(&g_edone[eslot], etarget);
    spinv(&g_bdone, 128);
    const int tid = threadIdx.x, lane = tid & 31, wid = tid >> 5;
    const int wm = wid & 3, wn = wid >> 2;
    const int NC = (2 * K) / 32;
    const uint32_t sbase = smem_u32(sm);
    uint32_t sA[2] = {sbase, sbase + 20480};
    uint32_t sB[2] = {sbase + 10240, sbase + 30720};

    const int arow = (lane & 7) + ((lane >> 3) & 1) * 8;
    const int akg = (lane >> 4) & 1;
    const int brow = (lane & 7) + ((lane >> 4) & 1) * 8;
    const int bkg = (lane >> 3) & 1;

    for (int m = mstart; m < mend; m++) {
        spinv(&g_dnb[dnbrow0 + m][n0 >> 7], nbtarget);
        const int shift = 3 - m;
        const uint32_t* wmp = w16 + (size_t)m * N4H * K;
        const uint32_t* aex = aexbase + (size_t)m * B_ * K;
        float acc[2][8][4];
#pragma unroll
        for (int i = 0; i < 2; i++)
#pragma unroll
            for (int j = 0; j < 8; j++)
#pragma unroll
                for (int q = 0; q < 4; q++) acc[i][j][q] = 0.0f;

        auto load = [&](int c) {
            int buf = c & 1;
            int kb2 = c * 16;
#pragma unroll
            for (int q = 0; q < 2; q++) {
                int idx = tid + q * 256;
                int row = idx >> 2, part = idx & 3;
                cpa16(sA[buf] + row * 80 + part * 16,
                      aex + (size_t)(b0 + row) * K + kb2 + part * 4);
                cpa16(sB[buf] + row * 80 + part * 16,
                      wmp + (size_t)(n0 + row) * K + kb2 + part * 4);
            }
            CPA_COMMIT();
        };

        load(0);
        for (int c = 0; c < NC; c++) {
            if (c + 1 < NC) {
                load(c + 1);
                asm volatile("cp.async.wait_group 1;" ::: "memory");
            } else {
                asm volatile("cp.async.wait_group 0;" ::: "memory");
            }
            __syncthreads();
            int buf = c & 1;
#pragma unroll
            for (int ks = 0; ks < 2; ks++) {
                uint32_t aF[2][4], bF[4][4];
#pragma unroll
                for (int mi = 0; mi < 2; mi++)
                    LDMX4(aF[mi], sA[buf] + (wm * 32 + mi * 16 + arow) * 80 +
                                      ks * 32 + akg * 16);
#pragma unroll
                for (int nj = 0; nj < 4; nj++)
                    LDMX4(bF[nj], sB[buf] + (wn * 64 + nj * 16 + brow) * 80 +
                                      ks * 32 + bkg * 16);
#pragma unroll
                for (int mi = 0; mi < 2; mi++)
#pragma unroll
                    for (int ni = 0; ni < 8; ni++)
                        HMMA(acc[mi][ni], aF[mi], bF[ni >> 1][(ni & 1) * 2],
                             bF[ni >> 1][(ni & 1) * 2 + 1]);
            }
            __syncthreads();
        }
#pragma unroll
        for (int mi = 0; mi < 2; mi++)
#pragma unroll
            for (int ni = 0; ni < 8; ni++) {
                int n = n0 + wn * 64 + ni * 8 + (lane & 3) * 2;
                float2 bqv = *(const float2*)&bq[m * N4H + n];
                float2 bnv = *(const float2*)&bn[m * N4H + n];
                int r0 = b0 + wm * 32 + mi * 16 + (lane >> 2);
                float x[4];
                x[0] = __fadd_rn(__fadd_rn(acc[mi][ni][0], bqv.x), bnv.x);
                x[1] = __fadd_rn(__fadd_rn(acc[mi][ni][1], bqv.y), bnv.y);
                x[2] = __fadd_rn(__fadd_rn(acc[mi][ni][2], bqv.x), bnv.x);
                x[3] = __fadd_rn(__fadd_rn(acc[mi][ni][3], bqv.y), bnv.y);
#pragma unroll
                for (int e = 0; e < 4; e++) {
                    int rb = (e < 2) ? r0 : r0 + 8;
                    int nn = n + (e & 1);
                    pb[(size_t)m * BN_SZ + (size_t)rb * N4H + nn] =
                        (unsigned char)(x[e] > 0.5f);
                    if (fabsf(x[e] - 0.5f) < EPSM) {
                        int idx = atomicAdd(cnt, 1);
                        if (idx < CAPF)
                            list[idx] = ((uint32_t)m << 24) |
                                        ((uint32_t)rb << 12) | (uint32_t)nn;
                    }
                }
            }
    }
    __threadfence();
    __syncthreads();
    if (tid == 0) atomicAdd(&g_mdone[mdslot], 1);
}

// ---------------- role: exact fixup (thread-per-entry) ----------------
__device__ void do_fixup(const unsigned char* __restrict__ codes, int K,
                         const float* __restrict__ wf32,
                         const float* __restrict__ bq, const float* __restrict__ bn,
                         unsigned char* __restrict__ pb,
                         const uint32_t* __restrict__ list, int* __restrict__ cnt,
                         int mdslot, int mdtarget, int lb, int nCTA, int fslot) {
    spinv(&g_mdone[mdslot], mdtarget);
    int total = min(*((volatile int*)cnt), CAPF);
    int nthr = nCTA * 256;
    for (int e = lb * 256 + threadIdx.x; e < total; e += nthr) {
        uint32_t ent = list[e];
        int m = ent >> 24, b = (ent >> 12) & 0xFFF, n = ent & 0xFFF;
        int shift = 3 - m;
        const float* wr = wf32 + ((size_t)m * N4H + n) * K;
        const unsigned char* cr = codes + (size_t)b * K;
        float acc = 0.0f;
        for (int k0 = 0; k0 < K; k0 += 16) {
            uint4 cc = *(const uint4*)(cr + k0);
            uint32_t word[4] = {cc.x, cc.y, cc.z, cc.w};
#pragma unroll
            for (int q = 0; q < 16; q++) {
                if ((word[q >> 2] >> ((q & 3) * 8 + shift)) & 1)
                    acc = __fadd_rn(acc, wr[k0 + q]);
            }
        }
        float x = __fadd_rn(__fadd_rn(acc, bq[m * N4H + n]), bn[m * N4H + n]);
        pb[(size_t)m * BN_SZ + (size_t)b * N4H + n] = (unsigned char)(x > 0.5f);
    }
    __threadfence();
    __syncthreads();
    if (threadIdx.x == 0) atomicAdd(&g_fdone[fslot], 1);
}

// ---------------- role: recombine + LSTM tail ----------------
__device__ __forceinline__ float clipa(float x, float aa) {
    return fminf(fmaxf(x, -aa), aa);
}
__device__ __forceinline__ float quantf(float x, float r) {
    float xs = fminf(fmaxf(__fdiv_rn(x, r), -0.9921875f), 0.9921875f);
    return __fmul_rn(__fmul_rn(rintf(__fmul_rn(xs, 128.0f)), 0.0078125f), r);
}
__device__ __forceinline__ float sigm(float x) {
    return __fadd_rn(0.5f, __fmul_rn(0.5f, tanhf(__fmul_rn(0.5f, x))));
}
__device__ __forceinline__ float partpb(const unsigned char* pb, size_t off, float a) {
    const float c0 = 8.0f/15.0f, c1 = 4.0f/15.0f, c2 = 2.0f/15.0f, c3 = 1.0f/15.0f;
    float s = __fmul_rn(c0, (float)pb[off]);
    s = __fadd_rn(s, __fmul_rn(c1, (float)pb[BN_SZ + off]));
    s = __fadd_rn(s, __fmul_rn(c2, (float)pb[2 * BN_SZ + off]));
    s = __fadd_rn(s, __fmul_rn(c3, (float)pb[3 * BN_SZ + off]));
    return __fsub_rn(__fmul_rn(s, __fmul_rn(a, 2.0f)), a);
}

__device__ void do_tail(int lb, const float* __restrict__ cx,
                        float* __restrict__ outh, float* __restrict__ outc,
                        const float* p1, const float* p3, const float* p4,
                        const float* p5, const float* p6, const float* p7,
                        const float* p8, const float* p9, const float* p10,
                        const float* p11) {
    if (threadIdx.x == 0) {
        while (*(volatile int*)&g_fdone[0] < 128) __nanosleep(100);
        while (*(volatile int*)&g_fdone[1] < 256) __nanosleep(100);
        __threadfence();
    }
    __syncthreads();
    int idx = lb * 256 + threadIdx.x;
    int b = idx >> 10, h = idx & 1023;
    float a1 = p1[0], a11v = p11[0];
    size_t o = (size_t)b * N4H;
    float gi = __fadd_rn(partpb(g_pb_ih, o + h, a1), partpb(g_pb_hh, o + h, a11v));
    float gj = __fadd_rn(partpb(g_pb_ih, o + H_ + h, a1),
                         partpb(g_pb_hh, o + H_ + h, a11v));
    float gf = __fadd_rn(partpb(g_pb_ih, o + 2*H_ + h, a1),
                         partpb(g_pb_hh, o + 2*H_ + h, a11v));
    float go = __fadd_rn(partpb(g_pb_ih, o + 3*H_ + h, a1),
                         partpb(g_pb_hh, o + 3*H_ + h, a11v));
    float a3 = p3[0], a4 = p4[0], a5 = p5[0], a6 = p6[0], a7 = p7[0];
    float a8 = p8[0], a9 = p9[0], a10 = p10[0];
    float fg  = quantf(clipa(sigm(gf), a3), a3);
    float ig  = quantf(clipa(sigm(gi), a4), a4);
    float act = quantf(clipa(tanhf(gj), a5), a5);
    float og  = quantf(clipa(sigm(go), a6), a6);
    float gc  = quantf(clipa(__fmul_rn(cx[idx], fg), a7), a7);
    float ai  = quantf(clipa(__fmul_rn(ig, act), a8), a8);
    float nc  = quantf(clipa(__fadd_rn(gc, ai), a9), a9);
    float acl = quantf(clipa(tanhf(nc), a10), a10);
    outh[idx] = quantf(clipa(__fmul_rn(acl, og), a11v), a11v);
    outc[idx] = nc;
}

// ---------------- fused pipeline kernel ----------------
// bid layout (monotone dispatch; spin deps at strictly lower bids):
// [0,96) maxred wih  [96,256) whh  [256,260) bih  [260,264) bhh -> pdone 264
// [264,520) code_in  [520,1544) code_hx                         -> cdone 1280
// [1544,1608) genb_ih  [1608,1672) genb_hh                      -> bdone 128
// [1672,1800) expand_ih (128)  -> edone[0] 128
// [1800,2312) expand_hh (512)  -> edone[1] 512
// [2312,6408) gen_ih (4 planes x 1024, nt-major)
// [6408,7432) mma_ih (1024, n-major, loops planes)
// [7432,7560) fixup_ih (128; waits mdone[0]==1024)
// p=0..3: base=7560+p*5120: gen_hh p (4096, nt-major) + mma_hh p (1024, n-major)
// [28040,28296) fixup_hh (256; waits mdone[1]==4096)
// [28296,44680) tail (16384)
__global__ __launch_bounds__(256, 2)
void k_fused(const float* __restrict__ w_ih, const float* __restrict__ w_hh,
             const float* __restrict__ input, const float* __restrict__ hx,
             const float* __restrict__ b_ih, const float* __restrict__ b_hh,
             uint32_t kw1a, uint32_t kw1b, uint32_t kb1a, uint32_t kb1b,
             uint32_t kw2a, uint32_t kw2b, uint32_t kb2a, uint32_t kb2b,
             const float* __restrict__ cx, float* __restrict__ outh,
             float* __restrict__ outc,
             const float* p1, const float* p3, const float* p4,
             const float* p5, const float* p6, const float* p7,
             const float* p8, const float* p9, const float* p10,
             const float* p11) {
    extern __shared__ char dsm[];
    const int bid = blockIdx.x;
    if (bid < 96) {
        do_maxred(bid, 96, w_ih, M_ * I_ * N4H, 0);
    } else if (bid < 256) {
        do_maxred(bid - 96, 160, w_hh, M_ * H_ * N4H, 1);
    } else if (bid < 260) {
        do_maxred(bid - 256, 4, b_ih, M_ * N4H, 2);
    } else if (bid < 264) {
        do_maxred(bid - 260, 4, b_hh, M_ * N4H, 3);
    } else if (bid < 520) {
        do_code(bid - 264, input, g_code_in, p1, p1);
    } else if (bid < 1544) {
        do_code(bid - 520, hx, g_code_hx, p11, p1);
    } else if (bid < 1608) {
        do_genb(bid - 1544, b_ih, g_bq_ih, g_bn_ih, kb1a, kb1b, 2);
    } else if (bid < 1672) {
        do_genb(bid - 1608, b_hh, g_bq_hh, g_bn_hh, kb2a, kb2b, 3);
    } else if (bid < 1800) {
        do_expand(bid - 1672, g_code_in, g_aex_ih, (size_t)B_ * I_, 0);
    } else if (bid < 2312) {
        do_expand(bid - 1800, g_code_hx, g_aex_hh, (size_t)B_ * H_, 1);
    } else if (bid < 6408) {
        int lb = bid - 2312;
        int m = lb >> 10, r = lb & 1023;
        do_gen(dsm, w_ih, g_wf32_ih, g_w16_ih, I_, kw1a, kw1b, 0,
               m, r & 7, r >> 3, m);
    } else if (bid < 7432) {
        int lb = bid - 6408;
        do_mma(dsm, g_aex_ih, I_, g_w16_ih, g_bq_ih, g_bn_ih, g_pb_ih,
               g_list0, &g_cnt[0], 0, 4, 0, 32,
               (lb >> 5) * 128, (lb & 31) * 128, 0, 0, 128);
    } else if (bid < 7560) {
        do_fixup(g_code_in, I_, g_wf32_ih, g_bq_ih, g_bn_ih, g_pb_ih,
                 g_list0, &g_cnt[0], 0, 1024, bid - 7432, 128, 0);
    } else if (bid < 28040) {
        int lb = bid - 7560;
        int p = lb / 5120, r = lb % 5120;
        if (r < 4096) {
            do_gen(dsm, w_hh, g_wf32_hh, g_w16_hh, H_, kw2a, kw2b, 1,
                   p, r & 31, r >> 5, 4 + p);
        } else {
            int q = r - 4096;
            do_mma(dsm, g_aex_hh, H_, g_w16_hh, g_bq_hh, g_bn_hh, g_pb_hh,
                   g_list1, &g_cnt[1], p, p + 1, 4, 128,
                   (q >> 5) * 128, (q & 31) * 128, 1, 1, 512);
        }
    } else if (bid < 28296) {
        do_fixup(g_code_hx, H_, g_wf32_hh, g_bq_hh, g_bn_hh, g_pb_hh,
                 g_list1, &g_cnt[1], 1, 4096, bid - 28040, 256, 1);
    } else {
        do_tail(bid - 28296, cx, outh, outc, p1, p3, p4, p5, p6, p7, p8, p9,
                p10, p11);
    }
}

// ---------------- launch ----------------
extern "C" void kernel_launch(void* const* d_in, const int* in_sizes, int n_in,
                              void* d_out, int out_size) {
    const float* input = (const float*)d_in[0];
    const float* hx    = (const float*)d_in[1];
    const float* cx    = (const float*)d_in[2];
    const float* w_ih  = (const float*)d_in[3];
    const float* w_hh  = (const float*)d_in[4];
    const float* b_ih  = (const float*)d_in[5];
    const float* b_hh  = (const float*)d_in[6];
    const float* a1  = (const float*)d_in[7];
    const float* a3  = (const float*)d_in[8];
    const float* a4  = (const float*)d_in[9];
    const float* a5  = (const float*)d_in[10];
    const float* a6  = (const float*)d_in[11];
    const float* a7  = (const float*)d_in[12];
    const float* a8  = (const float*)d_in[13];
    const float* a9  = (const float*)d_in[14];
    const float* a10 = (const float*)d_in[15];
    const float* a11 = (const float*)d_in[16];
    float* outh = (float*)d_out;
    float* outc = (float*)d_out + (size_t)B_ * H_;

    uint32_t k1a, k1b, k2a, k2b;
    tf2x32(0u, 42u, 0u, 0u, &k1a, &k1b);
    tf2x32(0u, 42u, 0u, 1u, &k2a, &k2b);
    uint32_t kw1a, kw1b, kb1a, kb1b, kw2a, kw2b, kb2a, kb2b;
    tf2x32(k1a, k1b, 0u, 0u, &kw1a, &kw1b);
    tf2x32(k1a, k1b, 0u, 1u, &kb1a, &kb1b);
    tf2x32(k2a, k2b, 0u, 0u, &kw2a, &kw2b);
    tf2x32(k2a, k2b, 0u, 1u, &kb2a, &kb2b);

    k_init<<<1, 256>>>();
    k_fused<<<44680, 256, 40960>>>(w_ih, w_hh, input, hx, b_ih, b_hh,
                                   kw1a, kw1b, kb1a, kb1b,
                                   kw2a, kw2b, kb2a, kb2b,
                                   cx, outh, outc,
                                   a1, a3, a4, a5, a6, a7, a8, a9, a10, a11);
}

// round 16
// speedup vs baseline: 1.1494x; 1.1494x over previous
#include <cuda_runtime.h>
#include <cuda_fp16.h>
#include <stdint.h>

#define B_ 4096
#define I_ 256
#define H_ 1024
#define N4H 4096
#define M_ 4
#define EPSM 1e-2f
#define CAPF (1<<20)
#define BN_SZ ((size_t)B_*N4H)

// ---------------- device scratch ----------------
__device__ float    g_wf32_ih[M_*N4H*I_];
__device__ float    g_wf32_hh[M_*N4H*H_];
__device__ uint32_t g_w16_ih[M_*N4H*I_];
__device__ uint32_t g_w16_hh[M_*N4H*H_];
__device__ float g_bq_ih[M_*N4H], g_bn_ih[M_*N4H], g_bq_hh[M_*N4H], g_bn_hh[M_*N4H];
__device__ unsigned char g_code_in[B_*I_], g_code_hx[B_*H_];
__device__ unsigned char g_pb_ih[4*BN_SZ];     // per-plane decision bytes
__device__ unsigned char g_pb_hh[4*BN_SZ];
__device__ float g_max[4];
__device__ int g_cnt[2];
__device__ int g_done[8];                      // ih planes 0-3, hh planes 4-7
__device__ uint32_t g_list0[CAPF], g_list1[CAPF];

// ---------------- threefry2x32 (JAX exact) ----------------
__host__ __device__ __forceinline__ uint32_t rotl32(uint32_t x, int r) {
    return (x << r) | (x >> (32 - r));
}
__host__ __device__ __forceinline__ void tf2x32(uint32_t k0, uint32_t k1,
                                                uint32_t x0, uint32_t x1,
                                                uint32_t* o0, uint32_t* o1) {
    uint32_t ks0 = k0, ks1 = k1, ks2 = k0 ^ k1 ^ 0x1BD11BDAu;
    x0 += ks0; x1 += ks1;
#define TF_RND(r) { x0 += x1; x1 = rotl32(x1, r); x1 ^= x0; }
    TF_RND(13) TF_RND(15) TF_RND(26) TF_RND(6)
    x0 += ks1; x1 += ks2 + 1u;
    TF_RND(17) TF_RND(29) TF_RND(16) TF_RND(24)
    x0 += ks2; x1 += ks0 + 2u;
    TF_RND(13) TF_RND(15) TF_RND(26) TF_RND(6)
    x0 += ks0; x1 += ks1 + 3u;
    TF_RND(17) TF_RND(29) TF_RND(16) TF_RND(24)
    x0 += ks1; x1 += ks2 + 4u;
    TF_RND(13) TF_RND(15) TF_RND(26) TF_RND(6)
    x0 += ks2; x1 += ks0 + 5u;
#undef TF_RND
    *o0 = x0; *o1 = x1;
}
// pipe-balanced device version (identical math)
__device__ __forceinline__ uint32_t rotl_mul(uint32_t x, int r) {
    uint64_t p = (uint64_t)x * (uint64_t)(1u << r);
    return (uint32_t)p | (uint32_t)(p >> 32);
}
__device__ __forceinline__ void tf2x32_bal(uint32_t k0, uint32_t k1,
                                           uint32_t x0, uint32_t x1,
                                           uint32_t* o0, uint32_t* o1) {
    uint32_t ks0 = k0, ks1 = k1, ks2 = k0 ^ k1 ^ 0x1BD11BDAu;
    x0 += ks0; x1 += ks1;
#define RA(r) { x0 += x1; x1 = rotl_mul(x1, r) ^ x0; }
#define RB(r) { x0 += x1; x1 = rotl32(x1, r) ^ x0; }
    RA(13) RB(15) RA(26) RB(6)
    x0 += ks1; x1 += ks2 + 1u;
    RA(17) RB(29) RA(16) RB(24)
    x0 += ks2; x1 += ks0 + 2u;
    RA(13) RB(15) RA(26) RB(6)
    x0 += ks0; x1 += ks1 + 3u;
    RA(17) RB(29) RA(16) RB(24)
    x0 += ks1; x1 += ks2 + 4u;
    RA(13) RB(15) RA(26) RB(6)
    x0 += ks2; x1 += ks0 + 5u;
#undef RA
#undef RB
    *o0 = x0; *o1 = x1;
}

__device__ __forceinline__ float erfinv_xla(float x) {
    float w = -log1pf(-__fmul_rn(x, x));
    float p;
    if (w < 5.0f) {
        w = w - 2.5f;
        p = 2.81022636e-08f;
        p = fmaf(p, w, 3.43273939e-07f);
        p = fmaf(p, w, -3.5233877e-06f);
        p = fmaf(p, w, -4.39150654e-06f);
        p = fmaf(p, w, 0.00021858087f);
        p = fmaf(p, w, -0.00125372503f);
        p = fmaf(p, w, -0.00417768164f);
        p = fmaf(p, w, 0.246640727f);
        p = fmaf(p, w, 1.50140941f);
    } else {
        w = sqrtf(w) - 3.0f;
        p = -0.000200214257f;
        p = fmaf(p, w, 0.000100950558f);
        p = fmaf(p, w, 0.00134934322f);
        p = fmaf(p, w, -0.00367342844f);
        p = fmaf(p, w, 0.00573950773f);
        p = fmaf(p, w, -0.0076224613f);
        p = fmaf(p, w, 0.00943887047f);
        p = fmaf(p, w, 1.00167406f);
        p = fmaf(p, w, 2.83297682f);
    }
    return __fmul_rn(p, x);
}
__device__ __forceinline__ float normal_from_bits(uint32_t bits) {
    float f = __uint_as_float((bits >> 9) | 0x3f800000u) - 1.0f;
    const float lo = -0.99999994f;
    float u = fmaxf(lo, __fadd_rn(__fmul_rn(f, 2.0f), lo));
    return __fmul_rn(1.41421356f, erfinv_xla(u));
}
__device__ __forceinline__ float quant8(float x) {
    float xs = fminf(fmaxf(x, -0.9921875f), 0.9921875f);
    return __fmul_rn(rintf(__fmul_rn(xs, 128.0f)), 0.0078125f);
}
__device__ __forceinline__ float weff_val(const float* W, int j, uint32_t k0,
                                          uint32_t k1, float wmax) {
    uint32_t o0, o1;
    tf2x32_bal(k0, k1, 0u, (uint32_t)j, &o0, &o1);
    float nrm = normal_from_bits(o0 ^ o1);
    return __fadd_rn(quant8(W[j]), __fmul_rn(__fmul_rn(nrm, wmax), 0.1f));
}

// ---------------- PTX helpers ----------------
__device__ __forceinline__ uint32_t smem_u32(const void* p) {
    uint32_t a;
    asm("{ .reg .u64 t; cvta.to.shared.u64 t, %1; cvt.u32.u64 %0, t; }" : "=r"(a) : "l"(p));
    return a;
}
__device__ __forceinline__ void cpa16(uint32_t dst, const void* src) {
    asm volatile("cp.async.cg.shared.global [%0], [%1], 16;" :: "r"(dst), "l"(src));
}
#define CPA_COMMIT() asm volatile("cp.async.commit_group;" ::: "memory")
#define LDMX4(r, a) asm volatile( \
    "ldmatrix.sync.aligned.m8n8.x4.shared.b16 {%0,%1,%2,%3}, [%4];" \
    : "=r"((r)[0]), "=r"((r)[1]), "=r"((r)[2]), "=r"((r)[3]) : "r"(a))
#define HMMA(c, a, bb0, bb1) asm volatile( \
    "mma.sync.aligned.m16n8k16.row.col.f32.f16.f16.f32 " \
    "{%0,%1,%2,%3},{%4,%5,%6,%7},{%8,%9},{%0,%1,%2,%3};" \
    : "+f"((c)[0]), "+f"((c)[1]), "+f"((c)[2]), "+f"((c)[3]) \
    : "r"((a)[0]), "r"((a)[1]), "r"((a)[2]), "r"((a)[3]), "r"(bb0), "r"(bb1))

__device__ __forceinline__ void spinwait(int slot, int target) {
    if (threadIdx.x == 0) {
        while (*(volatile int*)&g_done[slot] < target) __nanosleep(200);
        __threadfence();
    }
    __syncthreads();
}

// ---------------- small kernels ----------------
__global__ void k_init() {
    if (threadIdx.x < 4) g_max[threadIdx.x] = 0.0f;
    if (threadIdx.x < 2) g_cnt[threadIdx.x] = 0;
    if (threadIdx.x < 8) g_done[threadIdx.x] = 0;
}
__global__ void k_maxred(const float* __restrict__ x, int n, int slot) {
    float m = 0.0f;
    for (int i = blockIdx.x * blockDim.x + threadIdx.x; i < n;
         i += gridDim.x * blockDim.x)
        m = fmaxf(m, x[i]);
    for (int o = 16; o; o >>= 1)
        m = fmaxf(m, __shfl_xor_sync(0xffffffffu, m, o));
    if ((threadIdx.x & 31) == 0)
        atomicMax((int*)&g_max[slot], __float_as_int(m));
}
__global__ void k_genb(const float* __restrict__ bsrc, float* __restrict__ bq,
                       float* __restrict__ bn, int n, uint32_t k0, uint32_t k1,
                       int maxslot) {
    int j = blockIdx.x * blockDim.x + threadIdx.x;
    if (j >= n) return;
    uint32_t o0, o1;
    tf2x32_bal(k0, k1, 0u, (uint32_t)j, &o0, &o1);
    float nrm = normal_from_bits(o0 ^ o1);
    bq[j] = quant8(bsrc[j]);
    bn[j] = __fmul_rn(__fmul_rn(nrm, g_max[maxslot]), 0.1f);
}
__global__ void k_code(const float* __restrict__ x, unsigned char* __restrict__ code,
                       int n, const float* __restrict__ aclip,
                       const float* __restrict__ aoff) {
    int i = blockIdx.x * blockDim.x + threadIdx.x;
    if (i >= n) return;
    float ac = aclip[0], off = aoff[0];
    float xc = fminf(fmaxf(x[i], -ac), ac);
    float v01 = __fdiv_rn(__fadd_rn(xc, off), __fmul_rn(ac, 2.0f));
    int v = (int)rintf(__fmul_rn(15.0f, v01));
    code[i] = (unsigned char)(v & 15);
}

// ---------------- role: gen one 32k x 32n tile of plane m ----------------
__device__ void do_gen(const float* __restrict__ W, float* __restrict__ wf32,
                       uint32_t* __restrict__ w16, int K,
                       uint32_t key0, uint32_t key1, int maxslot,
                       int m, int kt, int nt, int doneslot) {
    __shared__ float tf[32][33];
    __shared__ uint32_t th[32][33];
    const int tid = threadIdx.x;
    const int kk0 = kt * 32, nn0 = nt * 32;
    const int tx = tid & 31, ty = tid >> 5;
    const float wmax = g_max[maxslot];
#pragma unroll
    for (int r = ty; r < 32; r += 8) {
        int j = (m * K + kk0 + r) * N4H + nn0 + tx;
        float w = weff_val(W, j, key0, key1, wmax);
        __half hi = __float2half_rn(w);
        float r1 = __fsub_rn(w, __half2float(hi));
        __half lo = __float2half_rn(r1);
        tf[r][tx] = w;
        th[r][tx] = (uint32_t)__half_as_ushort(hi) |
                    ((uint32_t)__half_as_ushort(lo) << 16);
    }
    __syncthreads();
#pragma unroll
    for (int r = ty; r < 32; r += 8) {
        size_t base = ((size_t)m * N4H + nn0 + r) * K + kk0 + tx;
        wf32[base] = tf[tx][r];
        w16[base] = th[tx][r];
    }
    __threadfence();
    __syncthreads();
    if (tid == 0) atomicAdd(&g_done[doneslot], 1);
}

// ---------------- role: HMMA 128x128 tile, planes [mstart,mend) --------------
__device__ void do_mma(const unsigned char* __restrict__ codes, int K,
                       const uint32_t* __restrict__ w16,
                       const float* __restrict__ bq, const float* __restrict__ bn,
                       unsigned char* __restrict__ pb,
                       uint32_t* __restrict__ list, int* __restrict__ cnt,
                       int mstart, int mend, int slot0, int target,
                       int n0, int b0) {
    __shared__ __align__(16) char sm[40960];
    const int tid = threadIdx.x, lane = tid & 31, wid = tid >> 5;
    const int wm = wid & 3, wn = wid >> 2;
    const int NC = (2 * K) / 32;
    const uint32_t sbase = smem_u32(sm);
    uint32_t sA[2] = {sbase, sbase + 20480};
    uint32_t sB[2] = {sbase + 10240, sbase + 30720};

    const int arow = (lane & 7) + ((lane >> 3) & 1) * 8;
    const int akg = (lane >> 4) & 1;
    const int brow = (lane & 7) + ((lane >> 4) & 1) * 8;
    const int bkg = (lane >> 3) & 1;
    const int erow = tid >> 1, eseg = tid & 1;

    for (int m = mstart; m < mend; m++) {
        spinwait(slot0 + m, target);
        const int shift = 3 - m;
        const uint32_t* wmp = w16 + (size_t)m * N4H * K;
        float acc[2][8][4];
#pragma unroll
        for (int i = 0; i < 2; i++)
#pragma unroll
            for (int j = 0; j < 8; j++)
#pragma unroll
                for (int q = 0; q < 4; q++) acc[i][j][q] = 0.0f;

        auto load = [&](int c) {
            int buf = c & 1;
            int kb2 = c * 16;
            {
                const unsigned char* cp =
                    codes + (size_t)(b0 + erow) * K + kb2 + eseg * 8;
                uint64_t cc = *(const uint64_t*)cp;
                uint32_t v[8];
#pragma unroll
                for (int q = 0; q < 8; q++)
                    v[q] = ((((uint32_t)(cc >> (8 * q))) >> shift) & 1u)
                               ? 0x3C003C00u : 0u;
                char* dst = sm + (buf ? 20480 : 0) + erow * 80 + eseg * 32;
                *(uint4*)dst = make_uint4(v[0], v[1], v[2], v[3]);
                *(uint4*)(dst + 16) = make_uint4(v[4], v[5], v[6], v[7]);
            }
#pragma unroll
            for (int q = 0; q < 2; q++) {
                int idx = tid + q * 256;
                int row = idx >> 2, part = idx & 3;
                const uint32_t* g = wmp + (size_t)(n0 + row) * K + kb2 + part * 4;
                cpa16(sB[buf] + row * 80 + part * 16, g);
            }
            CPA_COMMIT();
        };

        load(0);
        for (int c = 0; c < NC; c++) {
            if (c + 1 < NC) {
                load(c + 1);
                asm volatile("cp.async.wait_group 1;" ::: "memory");
            } else {
                asm volatile("cp.async.wait_group 0;" ::: "memory");
            }
            __syncthreads();
            int buf = c & 1;
#pragma unroll
            for (int ks = 0; ks < 2; ks++) {
                uint32_t aF[2][4], bF[4][4];
#pragma unroll
                for (int mi = 0; mi < 2; mi++)
                    LDMX4(aF[mi], sA[buf] + (wm * 32 + mi * 16 + arow) * 80 +
                                      ks * 32 + akg * 16);
#pragma unroll
                for (int nj = 0; nj < 4; nj++)
                    LDMX4(bF[nj], sB[buf] + (wn * 64 + nj * 16 + brow) * 80 +
                                      ks * 32 + bkg * 16);
#pragma unroll
                for (int mi = 0; mi < 2; mi++)
#pragma unroll
                    for (int ni = 0; ni < 8; ni++)
                        HMMA(acc[mi][ni], aF[mi], bF[ni >> 1][(ni & 1) * 2],
                             bF[ni >> 1][(ni & 1) * 2 + 1]);
            }
            __syncthreads();
        }
        // epilogue: threshold + margin flag -> per-plane bytes
#pragma unroll
        for (int mi = 0; mi < 2; mi++)
#pragma unroll
            for (int ni = 0; ni < 8; ni++) {
                int n = n0 + wn * 64 + ni * 8 + (lane & 3) * 2;
                float2 bqv = *(const float2*)&bq[m * N4H + n];
                float2 bnv = *(const float2*)&bn[m * N4H + n];
                int r0 = b0 + wm * 32 + mi * 16 + (lane >> 2);
                float x[4];
                x[0] = __fadd_rn(__fadd_rn(acc[mi][ni][0], bqv.x), bnv.x);
                x[1] = __fadd_rn(__fadd_rn(acc[mi][ni][1], bqv.y), bnv.y);
                x[2] = __fadd_rn(__fadd_rn(acc[mi][ni][2], bqv.x), bnv.x);
                x[3] = __fadd_rn(__fadd_rn(acc[mi][ni][3], bqv.y), bnv.y);
#pragma unroll
                for (int e = 0; e < 4; e++) {
                    int rb = (e < 2) ? r0 : r0 + 8;
                    int nn = n + (e & 1);
                    pb[(size_t)m * BN_SZ + (size_t)rb * N4H + nn] =
                        (unsigned char)(x[e] > 0.5f);
                    if (fabsf(x[e] - 0.5f) < EPSM) {
                        int idx = atomicAdd(cnt, 1);
                        if (idx < CAPF)
                            list[idx] = ((uint32_t)m << 24) |
                                        ((uint32_t)rb << 12) | (uint32_t)nn;
                    }
                }
            }
    }
}

// ---------------- fused pipeline kernel (R8 layout) ----------------
// [0,4096)      gen_ih planes 0-3 (1024 each)
// [4096,12288)  gen_hh planes 0-1 (4096 each)
// [12288,13312) mma_ih (4-plane loop)
// [13312,14336) mma_hh plane 0
// [14336,18432) gen_hh plane 2
// [18432,19456) mma_hh plane 1
// [19456,23552) gen_hh plane 3
// [23552,24576) mma_hh plane 2
// [24576,25600) mma_hh plane 3
__global__ __launch_bounds__(256, 2)
void k_fused(const float* __restrict__ w_ih, const float* __restrict__ w_hh,
             uint32_t kw1a, uint32_t kw1b, uint32_t kw2a, uint32_t kw2b) {
    const int bid = blockIdx.x;
    if (bid < 4096) {
        int m = bid >> 10, r = bid & 1023;
        do_gen(w_ih, g_wf32_ih, g_w16_ih, I_, kw1a, kw1b, 0,
               m, r & 7, r >> 3, m);
    } else if (bid < 12288) {
        int lb = bid - 4096;
        int m = lb >> 12, r = lb & 4095;
        do_gen(w_hh, g_wf32_hh, g_w16_hh, H_, kw2a, kw2b, 1,
               m, r & 31, r >> 5, 4 + m);
    } else if (bid < 13312) {
        int lb = bid - 12288;
        do_mma(g_code_in, I_, g_w16_ih, g_bq_ih, g_bn_ih, g_pb_ih,
               g_list0, &g_cnt[0], 0, 4, 0, 1024,
               (lb & 31) * 128, (lb >> 5) * 128);
    } else if (bid < 14336) {
        int lb = bid - 13312;
        do_mma(g_code_hx, H_, g_w16_hh, g_bq_hh, g_bn_hh, g_pb_hh,
               g_list1, &g_cnt[1], 0, 1, 4, 4096,
               (lb & 31) * 128, (lb >> 5) * 128);
    } else if (bid < 18432) {
        int r = bid - 14336;
        do_gen(w_hh, g_wf32_hh, g_w16_hh, H_, kw2a, kw2b, 1,
               2, r & 31, r >> 5, 6);
    } else if (bid < 19456) {
        int lb = bid - 18432;
        do_mma(g_code_hx, H_, g_w16_hh, g_bq_hh, g_bn_hh, g_pb_hh,
               g_list1, &g_cnt[1], 1, 2, 4, 4096,
               (lb & 31) * 128, (lb >> 5) * 128);
    } else if (bid < 23552) {
        int r = bid - 19456;
        do_gen(w_hh, g_wf32_hh, g_w16_hh, H_, kw2a, kw2b, 1,
               3, r & 31, r >> 5, 7);
    } else if (bid < 24576) {
        int lb = bid - 23552;
        do_mma(g_code_hx, H_, g_w16_hh, g_bq_hh, g_bn_hh, g_pb_hh,
               g_list1, &g_cnt[1], 2, 3, 4, 4096,
               (lb & 31) * 128, (lb >> 5) * 128);
    } else {
        int lb = bid - 24576;
        do_mma(g_code_hx, H_, g_w16_hh, g_bq_hh, g_bn_hh, g_pb_hh,
               g_list1, &g_cnt[1], 3, 4, 4, 4096,
               (lb & 31) * 128, (lb >> 5) * 128);
    }
}

// ---------------- exact fixup (thread-per-entry, plane-wise) ----------------
__global__ void k_fixup(const unsigned char* __restrict__ codes, int K,
                        const float* __restrict__ wf32,
                        const float* __restrict__ bq, const float* __restrict__ bn,
                        unsigned char* __restrict__ pb,
                        const uint32_t* __restrict__ list,
                        const int* __restrict__ cnt) {
    int total = min(*cnt, CAPF);
    int nthr = gridDim.x * blockDim.x;
    for (int e = blockIdx.x * blockDim.x + threadIdx.x; e < total; e += nthr) {
        uint32_t ent = list[e];
        int m = ent >> 24, b = (ent >> 12) & 0xFFF, n = ent & 0xFFF;
        int shift = 3 - m;
        const float* wr = wf32 + ((size_t)m * N4H + n) * K;
        const unsigned char* cr = codes + (size_t)b * K;
        float acc = 0.0f;
        for (int k0 = 0; k0 < K; k0 += 16) {
            uint4 cc = *(const uint4*)(cr + k0);
            uint32_t word[4] = {cc.x, cc.y, cc.z, cc.w};
#pragma unroll
            for (int q = 0; q < 16; q++) {
                if ((word[q >> 2] >> ((q & 3) * 8 + shift)) & 1)
                    acc = __fadd_rn(acc, wr[k0 + q]);
            }
        }
        float x = __fadd_rn(__fadd_rn(acc, bq[m * N4H + n]), bn[m * N4H + n]);
        pb[(size_t)m * BN_SZ + (size_t)b * N4H + n] = (unsigned char)(x > 0.5f);
    }
}

// ---------------- fused recombine + LSTM tail ----------------
__device__ __forceinline__ float clipa(float x, float aa) {
    return fminf(fmaxf(x, -aa), aa);
}
__device__ __forceinline__ float quantf(float x, float r) {
    float xs = fminf(fmaxf(__fdiv_rn(x, r), -0.9921875f), 0.9921875f);
    return __fmul_rn(__fmul_rn(rintf(__fmul_rn(xs, 128.0f)), 0.0078125f), r);
}
__device__ __forceinline__ float sigm(float x) {
    return __fadd_rn(0.5f, __fmul_rn(0.5f, tanhf(__fmul_rn(0.5f, x))));
}
__device__ __forceinline__ float partpb(const unsigned char* pb, size_t off, float a) {
    const float c0 = 8.0f/15.0f, c1 = 4.0f/15.0f, c2 = 2.0f/15.0f, c3 = 1.0f/15.0f;
    float s = __fmul_rn(c0, (float)pb[off]);
    s = __fadd_rn(s, __fmul_rn(c1, (float)pb[BN_SZ + off]));
    s = __fadd_rn(s, __fmul_rn(c2, (float)pb[2 * BN_SZ + off]));
    s = __fadd_rn(s, __fmul_rn(c3, (float)pb[3 * BN_SZ + off]));
    return __fsub_rn(__fmul_rn(s, __fmul_rn(a, 2.0f)), a);
}

__global__ void k_tail(const float* __restrict__ cx, float* __restrict__ outh,
                       float* __restrict__ outc, const float* p1, const float* p3,
                       const float* p4, const float* p5, const float* p6,
                       const float* p7, const float* p8, const float* p9,
                       const float* p10, const float* p11) {
    int idx = blockIdx.x * blockDim.x + threadIdx.x;
    if (idx >= B_ * H_) return;
    int b = idx >> 10, h = idx & 1023;
    float a1 = p1[0], a11v = p11[0];
    size_t o = (size_t)b * N4H;
    float gi = __fadd_rn(partpb(g_pb_ih, o + h, a1), partpb(g_pb_hh, o + h, a11v));
    float gj = __fadd_rn(partpb(g_pb_ih, o + H_ + h, a1),
                         partpb(g_pb_hh, o + H_ + h, a11v));
    float gf = __fadd_rn(partpb(g_pb_ih, o + 2*H_ + h, a1),
                         partpb(g_pb_hh, o + 2*H_ + h, a11v));
    float go = __fadd_rn(partpb(g_pb_ih, o + 3*H_ + h, a1),
                         partpb(g_pb_hh, o + 3*H_ + h, a11v));
    float a3 = p3[0], a4 = p4[0], a5 = p5[0], a6 = p6[0], a7 = p7[0];
    float a8 = p8[0], a9 = p9[0], a10 = p10[0];
    float fg  = quantf(clipa(sigm(gf), a3), a3);
    float ig  = quantf(clipa(sigm(gi), a4), a4);
    float act = quantf(clipa(tanhf(gj), a5), a5);
    float og  = quantf(clipa(sigm(go), a6), a6);
    float gc  = quantf(clipa(__fmul_rn(cx[idx], fg), a7), a7);
    float ai  = quantf(clipa(__fmul_rn(ig, act), a8), a8);
    float nc  = quantf(clipa(__fadd_rn(gc, ai), a9), a9);
    float acl = quantf(clipa(tanhf(nc), a10), a10);
    outh[idx] = quantf(clipa(__fmul_rn(acl, og), a11v), a11v);
    outc[idx] = nc;
}

// ---------------- launch ----------------
extern "C" void kernel_launch(void* const* d_in, const int* in_sizes, int n_in,
                              void* d_out, int out_size) {
    const float* input = (const float*)d_in[0];
    const float* hx    = (const float*)d_in[1];
    const float* cx    = (const float*)d_in[2];
    const float* w_ih  = (const float*)d_in[3];
    const float* w_hh  = (const float*)d_in[4];
    const float* b_ih  = (const float*)d_in[5];
    const float* b_hh  = (const float*)d_in[6];
    const float* a1  = (const float*)d_in[7];
    const float* a3  = (const float*)d_in[8];
    const float* a4  = (const float*)d_in[9];
    const float* a5  = (const float*)d_in[10];
    const float* a6  = (const float*)d_in[11];
    const float* a7  = (const float*)d_in[12];
    const float* a8  = (const float*)d_in[13];
    const float* a9  = (const float*)d_in[14];
    const float* a10 = (const float*)d_in[15];
    const float* a11 = (const float*)d_in[16];
    float* outh = (float*)d_out;
    float* outc = (float*)d_out + (size_t)B_ * H_;

    uint32_t k1a, k1b, k2a, k2b;
    tf2x32(0u, 42u, 0u, 0u, &k1a, &k1b);
    tf2x32(0u, 42u, 0u, 1u, &k2a, &k2b);
    uint32_t kw1a, kw1b, kb1a, kb1b, kw2a, kw2b, kb2a, kb2b;
    tf2x32(k1a, k1b, 0u, 0u, &kw1a, &kw1b);
    tf2x32(k1a, k1b, 0u, 1u, &kb1a, &kb1b);
    tf2x32(k2a, k2b, 0u, 0u, &kw2a, &kw2b);
    tf2x32(k2a, k2b, 0u, 1u, &kb2a, &kb2b);

    float *pwf_ih, *pwf_hh, *pbq_ih, *pbn_ih, *pbq_hh, *pbn_hh;
    unsigned char *pcode_in, *pcode_hx, *ppb_ih, *ppb_hh;
    uint32_t *plist0, *plist1;
    int* pcnt;
    cudaGetSymbolAddress((void**)&pwf_ih, g_wf32_ih);
    cudaGetSymbolAddress((void**)&pwf_hh, g_wf32_hh);
    cudaGetSymbolAddress((void**)&pbq_ih, g_bq_ih);
    cudaGetSymbolAddress((void**)&pbn_ih, g_bn_ih);
    cudaGetSymbolAddress((void**)&pbq_hh, g_bq_hh);
    cudaGetSymbolAddress((void**)&pbn_hh, g_bn_hh);
    cudaGetSymbolAddress((void**)&pcode_in, g_code_in);
    cudaGetSymbolAddress((void**)&pcode_hx, g_code_hx);
    cudaGetSymbolAddress((void**)&ppb_ih, g_pb_ih);
    cudaGetSymbolAddress((void**)&ppb_hh, g_pb_hh);
    cudaGetSymbolAddress((void**)&plist0, g_list0);
    cudaGetSymbolAddress((void**)&plist1, g_list1);
    cudaGetSymbolAddress((void**)&pcnt, g_cnt);

    const int nb = M_ * N4H;
    k_init<<<1, 32>>>();
    k_maxred<<<512, 256>>>(w_ih, M_ * I_ * N4H, 0);
    k_maxred<<<512, 256>>>(w_hh, M_ * H_ * N4H, 1);
    k_maxred<<<64, 256>>>(b_ih, nb, 2);
    k_maxred<<<64, 256>>>(b_hh, nb, 3);
    k_genb<<<(nb + 255) / 256, 256>>>(b_ih, pbq_ih, pbn_ih, nb, kb1a, kb1b, 2);
    k_genb<<<(nb + 255) / 256, 256>>>(b_hh, pbq_hh, pbn_hh, nb, kb2a, kb2b, 3);
    k_code<<<(B_ * I_ + 255) / 256, 256>>>(input, pcode_in, B_ * I_, a1, a1);
    k_code<<<(B_ * H_ + 255) / 256, 256>>>(hx, pcode_hx, B_ * H_, a11, a1);

    k_fused<<<25600, 256>>>(w_ih, w_hh, kw1a, kw1b, kw2a, kw2b);

    k_fixup<<<256, 256>>>(pcode_in, I_, pwf_ih, pbq_ih, pbn_ih, ppb_ih,
                          plist0, pcnt);
    k_fixup<<<256, 256>>>(pcode_hx, H_, pwf_hh, pbq_hh, pbn_hh, ppb_hh,
                          plist1, pcnt + 1);

    k_tail<<<(B_ * H_ + 255) / 256, 256>>>(cx, outh, outc, a1, a3, a4, a5, a6,
                                           a7, a8, a9, a10, a11);
}